// round 3
// baseline (speedup 1.0000x reference)
#include <cuda_runtime.h>
#include <math.h>

// Problem constants
#define BB 4096
#define CC 1000
#define PP 10
#define DD 256
#define NN 10000     // CC*PP
#define EE 160000
#define MARGIN_F (-0.1f)
#define LW_F (0.1f)

// ---------------- scratch (device globals; no runtime allocation) ----------------
__device__ float g_bufA[NN * DD];       // xw scratch
__device__ float g_bufB[NN * DD];       // aggregated / x / proto_norm
__device__ float g_hn[BB * DD];         // hidden_norm
__device__ float g_sim[(size_t)BB * NN];// raw dot products (160MB)
__device__ unsigned char g_argp[BB * CC];
__device__ float g_disqrt[NN];
__device__ int   g_deg[NN];
__device__ int   g_rowptr[NN + 1];
__device__ int   g_col[EE];
__device__ int   g_cursor[NN];
__device__ float g_wt[DD * DD];
__device__ float g_s[DD];
__device__ float g_ce_sum;
__device__ int   g_cnt;

// ---------------- init ----------------
__global__ void init_kernel(float* out_tail /* d_out + BB*CC : loss + usages */) {
    int i = blockIdx.x * blockDim.x + threadIdx.x;
    if (i < NN) { g_deg[i] = 0; g_cursor[i] = 0; }
    if (i < DD) g_s[i] = 0.0f;
    if (i == 0) { g_ce_sum = 0.0f; g_cnt = 0; }
    if (i < 1 + 2 * NN) out_tail[i] = 0.0f;
}

// ---------------- degree (edges only; self-loop added later) ----------------
__global__ void deg_kernel(const int* __restrict__ ei) {
    int e = blockIdx.x * blockDim.x + threadIdx.x;
    if (e < EE) atomicAdd(&g_deg[ei[EE + e]], 1);
}

__global__ void disqrt_kernel() {
    int n = blockIdx.x * blockDim.x + threadIdx.x;
    if (n < NN) {
        float x = (float)(g_deg[n] + 1);     // + self loop
        float r = rsqrtf(x);
        r = r * (1.5f - 0.5f * x * r * r);   // Newton refine
        g_disqrt[n] = r;
    }
}

// ---------------- exclusive scan of g_deg -> g_rowptr (one block) ----------------
__global__ void scan_kernel() {
    const int T = 1024;
    const int CH = (NN + T - 1) / T; // 10
    __shared__ int part[T];
    int t = threadIdx.x;
    int base = t * CH;
    int s = 0;
    for (int i = 0; i < CH; i++) {
        int idx = base + i;
        if (idx < NN) s += g_deg[idx];
    }
    part[t] = s;
    __syncthreads();
    for (int off = 1; off < T; off <<= 1) {
        int add = (t >= off) ? part[t - off] : 0;
        __syncthreads();
        part[t] += add;
        __syncthreads();
    }
    if (t == 0) g_rowptr[NN] = part[T - 1];
    int prefix = (t > 0) ? part[t - 1] : 0;
    for (int i = 0; i < CH; i++) {
        int idx = base + i;
        if (idx < NN) { g_rowptr[idx] = prefix; prefix += g_deg[idx]; }
    }
}

__global__ void scatter_kernel(const int* __restrict__ ei) {
    int e = blockIdx.x * blockDim.x + threadIdx.x;
    if (e < EE) {
        int d = ei[EE + e];
        int pos = g_rowptr[d] + atomicAdd(&g_cursor[d], 1);
        g_col[pos] = ei[e]; // src
    }
}

// sort each node's adjacency for deterministic summation order
__global__ void sort_kernel() {
    int n = blockIdx.x * blockDim.x + threadIdx.x;
    if (n >= NN) return;
    int beg = g_rowptr[n], end = g_rowptr[n + 1];
    for (int i = beg + 1; i < end; i++) {
        int key = g_col[i];
        int j = i - 1;
        while (j >= beg && g_col[j] > key) { g_col[j + 1] = g_col[j]; j--; }
        g_col[j + 1] = key;
    }
}

// ---------------- weight transpose: g_wt[j*D+k] = w[k*D+j] ----------------
__global__ void transpose_kernel(const float* __restrict__ w, float* __restrict__ wt) {
    int i = blockIdx.x * blockDim.x + threadIdx.x;
    if (i < DD * DD) {
        int r = i >> 8, c = i & 255;
        wt[c * DD + r] = w[i];
    }
}

// ---------------- SGEMM: C[M,Nn] = A[M,256] @ Bt[Nn,256]^T ----------------
#define BM 128
#define BN 128
#define BK 16
__global__ __launch_bounds__(256) void sgemm_nt(const float* __restrict__ A,
                                                const float* __restrict__ Bt,
                                                float* __restrict__ Cc,
                                                int M, int Nn) {
    __shared__ float As[BK][BM + 4];
    __shared__ float Bs[BK][BN + 4];
    int bm = blockIdx.y * BM;
    int bn = blockIdx.x * BN;
    int tid = threadIdx.x;
    int tr = tid >> 4;       // 0..15
    int tc = tid & 15;       // 0..15
    float acc[8][8];
#pragma unroll
    for (int i = 0; i < 8; i++)
#pragma unroll
        for (int j = 0; j < 8; j++) acc[i][j] = 0.0f;

    int lrow = tid >> 1;          // 0..127
    int lkq = (tid & 1) * 2;      // 0 or 2 (float4 idx within 16 k)

    for (int k0 = 0; k0 < DD; k0 += BK) {
        // load A tile [128 x 16]
#pragma unroll
        for (int q = 0; q < 2; q++) {
            float4 v = make_float4(0.f, 0.f, 0.f, 0.f);
            int gr = bm + lrow;
            if (gr < M) v = *(const float4*)&A[(size_t)gr * DD + k0 + (lkq + q) * 4];
            int kb = (lkq + q) * 4;
            As[kb + 0][lrow] = v.x;
            As[kb + 1][lrow] = v.y;
            As[kb + 2][lrow] = v.z;
            As[kb + 3][lrow] = v.w;
        }
        // load B tile [128 x 16]
#pragma unroll
        for (int q = 0; q < 2; q++) {
            float4 v = make_float4(0.f, 0.f, 0.f, 0.f);
            int gn = bn + lrow;
            if (gn < Nn) v = *(const float4*)&Bt[(size_t)gn * DD + k0 + (lkq + q) * 4];
            int kb = (lkq + q) * 4;
            Bs[kb + 0][lrow] = v.x;
            Bs[kb + 1][lrow] = v.y;
            Bs[kb + 2][lrow] = v.z;
            Bs[kb + 3][lrow] = v.w;
        }
        __syncthreads();
#pragma unroll
        for (int kk = 0; kk < BK; kk++) {
            float a[8], b[8];
#pragma unroll
            for (int i = 0; i < 8; i++) a[i] = As[kk][tr * 8 + i];
#pragma unroll
            for (int j = 0; j < 8; j++) b[j] = Bs[kk][tc * 8 + j];
#pragma unroll
            for (int i = 0; i < 8; i++)
#pragma unroll
                for (int j = 0; j < 8; j++) acc[i][j] = fmaf(a[i], b[j], acc[i][j]);
        }
        __syncthreads();
    }
#pragma unroll
    for (int i = 0; i < 8; i++) {
        int gr = bm + tr * 8 + i;
        if (gr >= M) continue;
#pragma unroll
        for (int j = 0; j < 8; j++) {
            int gn = bn + tc * 8 + j;
            if (gn < Nn) Cc[(size_t)gr * Nn + gn] = acc[i][j];
        }
    }
}

// ---------------- GCN aggregation + bias + relu ----------------
__global__ void agg_kernel(const float* __restrict__ xw,
                           float* __restrict__ outp,
                           const float* __restrict__ bias) {
    int n = blockIdx.x;
    int d = threadIdx.x; // 256 = DD
    float dn = g_disqrt[n];
    float acc = dn * dn * xw[(size_t)n * DD + d];
    int beg = g_rowptr[n], end = g_rowptr[n + 1];
    for (int j = beg; j < end; j++) {
        int s = g_col[j];
        acc += dn * g_disqrt[s] * xw[(size_t)s * DD + d];
    }
    outp[(size_t)n * DD + d] = fmaxf(acc + bias[d], 0.0f);
}

// ---------------- row L2 normalize (optionally accumulate column sums) ----------------
__global__ void norm_rows_kernel(const float* __restrict__ in,
                                 float* __restrict__ outp, int accum_s) {
    int r = blockIdx.x;
    int t = threadIdx.x;
    float v = in[(size_t)r * DD + t];
    __shared__ float sh[DD];
    sh[t] = v * v;
    __syncthreads();
    for (int off = 128; off > 0; off >>= 1) {
        if (t < off) sh[t] += sh[t + off];
        __syncthreads();
    }
    float nrm = sqrtf(sh[0]);
    float val = v / fmaxf(nrm, 1e-12f);
    outp[(size_t)r * DD + t] = val;
    if (accum_s) atomicAdd(&g_s[t], val);
}

// ---------------- per-class max over 10 prototypes ----------------
__global__ void reduce_max_kernel(float* __restrict__ out) {
    int i = blockIdx.x * blockDim.x + threadIdx.x;
    if (i >= BB * CC) return;
    int b = i / CC, c = i % CC;
    const float* p = &g_sim[(size_t)b * NN + c * PP];
    float best = -1e30f;
    int bi = 0;
#pragma unroll
    for (int j = 0; j < PP; j++) {
        float v = p[j];
        if (v > best) { best = v; bi = j; }
    }
    out[i] = 0.5f * (1.0f + best);
    g_argp[i] = (unsigned char)bi;
}

// ---------------- per-row CE + usage scatter ----------------
__global__ void ce_kernel(const float* __restrict__ out,
                          const int* __restrict__ labels,
                          float* __restrict__ usage_pos,
                          float* __restrict__ usage_neg) {
    int b = blockIdx.x;
    const float* row = out + (size_t)b * CC;
    int t = threadIdx.x;
    __shared__ float smax[256];
    __shared__ int simax[256];
    float bm = -1e30f;
    int bi = 0x7fffffff;
    for (int c = t; c < CC; c += 256) {
        float v = row[c];
        if (v > bm) { bm = v; bi = c; }
    }
    smax[t] = bm; simax[t] = bi;
    __syncthreads();
    for (int off = 128; off > 0; off >>= 1) {
        if (t < off) {
            float v2 = smax[t + off];
            int i2 = simax[t + off];
            if (v2 > smax[t] || (v2 == smax[t] && i2 < simax[t])) {
                smax[t] = v2; simax[t] = i2;
            }
        }
        __syncthreads();
    }
    float rowmax = smax[0];
    int pred = simax[0];
    __shared__ float ssum[256];
    float s = 0.0f;
    for (int c = t; c < CC; c += 256) s += expf(row[c] - rowmax);
    ssum[t] = s;
    __syncthreads();
    for (int off = 128; off > 0; off >>= 1) {
        if (t < off) ssum[t] += ssum[t + off];
        __syncthreads();
    }
    if (t == 0) {
        int lab = labels[b];
        float x_lab = row[lab];
        float lse = rowmax + logf(ssum[0]);
        if ((x_lab - rowmax) > MARGIN_F) {
            atomicAdd(&g_ce_sum, lse - x_lab);
            atomicAdd(&g_cnt, 1);
        }
        atomicAdd(&usage_pos[lab * PP + (int)g_argp[b * CC + lab]], 1.0f);
        if (pred != lab)
            atomicAdd(&usage_neg[pred * PP + (int)g_argp[b * CC + pred]], 1.0f);
    }
}

// ---------------- finalize loss ----------------
__global__ void finalize_kernel(float* __restrict__ out_loss) {
    __shared__ float sh[DD];
    int t = threadIdx.x;
    float v = g_s[t];
    sh[t] = v * v;
    __syncthreads();
    for (int off = 128; off > 0; off >>= 1) {
        if (t < off) sh[t] += sh[t + off];
        __syncthreads();
    }
    if (t == 0) {
        float disp = -sh[0] / ((float)NN * (float)NN);
        int cnt = g_cnt;
        float loss = (cnt == 0) ? 0.0f
                                : (g_ce_sum / (float)(cnt > 1 ? cnt : 1) + LW_F * disp);
        out_loss[0] = loss;
    }
}

// ---------------- launch ----------------
extern "C" void kernel_launch(void* const* d_in, const int* in_sizes, int n_in,
                              void* d_out, int out_size) {
    const float* hidden = (const float*)d_in[0];
    const int* labels = (const int*)d_in[1];
    const int* edge_index = (const int*)d_in[2];
    const float* node_features = (const float*)d_in[3];
    const float* w1 = (const float*)d_in[4];
    const float* b1 = (const float*)d_in[5];
    const float* w2 = (const float*)d_in[6];
    const float* b2 = (const float*)d_in[7];
    float* out = (float*)d_out;

    float* out_loss = out + (size_t)BB * CC;
    float* out_pos = out_loss + 1;
    float* out_neg = out_pos + NN;

    // Resolve device-global scratch addresses (host-side query; capture-safe,
    // no allocation, deterministic).
    float *p_bufA = 0, *p_bufB = 0, *p_hn = 0, *p_sim = 0, *p_wt = 0;
    cudaGetSymbolAddress((void**)&p_bufA, g_bufA);
    cudaGetSymbolAddress((void**)&p_bufB, g_bufB);
    cudaGetSymbolAddress((void**)&p_hn,   g_hn);
    cudaGetSymbolAddress((void**)&p_sim,  g_sim);
    cudaGetSymbolAddress((void**)&p_wt,   g_wt);

    // graph build
    init_kernel<<<(1 + 2 * NN + 255) / 256, 256>>>(out_loss);
    deg_kernel<<<(EE + 255) / 256, 256>>>(edge_index);
    disqrt_kernel<<<(NN + 255) / 256, 256>>>();
    scan_kernel<<<1, 1024>>>();
    scatter_kernel<<<(EE + 255) / 256, 256>>>(edge_index);
    sort_kernel<<<(NN + 255) / 256, 256>>>();

    // GCN layer 1: xw = x @ w1 ; aggregate + bias + relu
    transpose_kernel<<<(DD * DD + 255) / 256, 256>>>(w1, p_wt);
    {
        dim3 grid((DD + BN - 1) / BN, (NN + BM - 1) / BM);
        sgemm_nt<<<grid, 256>>>(node_features, p_wt, p_bufA, NN, DD);
    }
    agg_kernel<<<NN, DD>>>(p_bufA, p_bufB, b1);
    // GCN layer 2
    transpose_kernel<<<(DD * DD + 255) / 256, 256>>>(w2, p_wt);
    {
        dim3 grid((DD + BN - 1) / BN, (NN + BM - 1) / BM);
        sgemm_nt<<<grid, 256>>>(p_bufB, p_wt, p_bufA, NN, DD);
    }
    agg_kernel<<<NN, DD>>>(p_bufA, p_bufB, b2);

    // normalize prototypes (in place, accumulate column sums) and hidden
    norm_rows_kernel<<<NN, DD>>>(p_bufB, p_bufB, 1);
    norm_rows_kernel<<<BB, DD>>>(hidden, p_hn, 0);

    // big similarity GEMM: g_sim[B,N] = hn @ proto_norm^T
    {
        dim3 grid((NN + BN - 1) / BN, (BB + BM - 1) / BM);
        sgemm_nt<<<grid, 256>>>(p_hn, p_bufB, p_sim, BB, NN);
    }

    // per-class max + argmax
    reduce_max_kernel<<<(BB * CC + 255) / 256, 256>>>(out);

    // CE + usage
    ce_kernel<<<BB, 256>>>(out, labels, out_pos, out_neg);

    // loss
    finalize_kernel<<<1, DD>>>(out_loss);
}

// round 6
// speedup vs baseline: 1.5341x; 1.5341x over previous
#include <cuda_runtime.h>
#include <cuda_bf16.h>
#include <math.h>
#include <stdint.h>

// Problem constants
#define BB 4096
#define CC 1000
#define PP 10
#define DD 256
#define NN 10000     // CC*PP
#define EE 160000
#define MARGIN_F (-0.1f)
#define LW_F (0.1f)

// bf16-split GEMM geometry
#define KTOT 768          // [hi | hi | lo] x [hi | lo | hi]
#define LDN 10112         // N padded to 79*128

// ---------------- scratch (device globals; no runtime allocation) ----------------
__device__ float g_bufA[NN * DD];               // xw scratch
__device__ float g_bufB[NN * DD];               // aggregated / x
__device__ __nv_bfloat16 g_Abf[BB * KTOT];      // hidden_norm split
__device__ __nv_bfloat16 g_Bbf[LDN * KTOT];     // proto_norm split (pad rows stay 0)
__device__ float g_sim[(size_t)BB * LDN];       // raw dot products
__device__ unsigned char g_argp[BB * CC];
__device__ float g_disqrt[NN];
__device__ int   g_deg[NN];
__device__ int   g_rowptr[NN + 1];
__device__ int   g_col[EE];
__device__ int   g_cursor[NN];
__device__ float g_wt[DD * DD];
__device__ float g_s[DD];
__device__ float g_ce_sum;
__device__ int   g_cnt;

// ---------------- helpers ----------------
__device__ __forceinline__ uint32_t smem_to_u32(const void* p) {
    uint32_t a;
    asm("{ .reg .u64 t; cvta.to.shared.u64 t, %1; cvt.u32.u64 %0, t; }" : "=r"(a) : "l"(p));
    return a;
}
__device__ __forceinline__ void cp_async16(uint32_t dst, const void* src) {
    asm volatile("cp.async.cg.shared.global [%0], [%1], 16;" :: "r"(dst), "l"(src) : "memory");
}
__device__ __forceinline__ void cp_commit() {
    asm volatile("cp.async.commit_group;" ::: "memory");
}
__device__ __forceinline__ void cp_wait0() {
    asm volatile("cp.async.wait_group 0;" ::: "memory");
}
__device__ __forceinline__ void ldm_x4(uint32_t& r0, uint32_t& r1, uint32_t& r2, uint32_t& r3,
                                       uint32_t addr) {
    asm volatile("ldmatrix.sync.aligned.m8n8.x4.shared.b16 {%0,%1,%2,%3}, [%4];"
                 : "=r"(r0), "=r"(r1), "=r"(r2), "=r"(r3) : "r"(addr));
}
__device__ __forceinline__ void mma16816(float* d, const uint32_t* a, const uint32_t* b) {
    asm volatile(
        "mma.sync.aligned.m16n8k16.row.col.f32.bf16.bf16.f32 "
        "{%0,%1,%2,%3}, {%4,%5,%6,%7}, {%8,%9}, {%0,%1,%2,%3};"
        : "+f"(d[0]), "+f"(d[1]), "+f"(d[2]), "+f"(d[3])
        : "r"(a[0]), "r"(a[1]), "r"(a[2]), "r"(a[3]), "r"(b[0]), "r"(b[1]));
}

// ---------------- init ----------------
__global__ void init_kernel(float* out_tail) {
    int i = blockIdx.x * blockDim.x + threadIdx.x;
    if (i < NN) { g_deg[i] = 0; g_cursor[i] = 0; }
    if (i < DD) g_s[i] = 0.0f;
    if (i == 0) { g_ce_sum = 0.0f; g_cnt = 0; }
    if (i < 1 + 2 * NN) out_tail[i] = 0.0f;
}

// ---------------- degree ----------------
__global__ void deg_kernel(const int* __restrict__ ei) {
    int e = blockIdx.x * blockDim.x + threadIdx.x;
    if (e < EE) atomicAdd(&g_deg[ei[EE + e]], 1);
}

__global__ void disqrt_kernel() {
    int n = blockIdx.x * blockDim.x + threadIdx.x;
    if (n < NN) {
        float x = (float)(g_deg[n] + 1);
        float r = rsqrtf(x);
        r = r * (1.5f - 0.5f * x * r * r);
        g_disqrt[n] = r;
    }
}

// ---------------- exclusive scan ----------------
__global__ void scan_kernel() {
    const int T = 1024;
    const int CH = (NN + T - 1) / T;
    __shared__ int part[T];
    int t = threadIdx.x;
    int base = t * CH;
    int s = 0;
    for (int i = 0; i < CH; i++) {
        int idx = base + i;
        if (idx < NN) s += g_deg[idx];
    }
    part[t] = s;
    __syncthreads();
    for (int off = 1; off < T; off <<= 1) {
        int add = (t >= off) ? part[t - off] : 0;
        __syncthreads();
        part[t] += add;
        __syncthreads();
    }
    if (t == 0) g_rowptr[NN] = part[T - 1];
    int prefix = (t > 0) ? part[t - 1] : 0;
    for (int i = 0; i < CH; i++) {
        int idx = base + i;
        if (idx < NN) { g_rowptr[idx] = prefix; prefix += g_deg[idx]; }
    }
}

__global__ void scatter_kernel(const int* __restrict__ ei) {
    int e = blockIdx.x * blockDim.x + threadIdx.x;
    if (e < EE) {
        int d = ei[EE + e];
        int pos = g_rowptr[d] + atomicAdd(&g_cursor[d], 1);
        g_col[pos] = ei[e];
    }
}

__global__ void sort_kernel() {
    int n = blockIdx.x * blockDim.x + threadIdx.x;
    if (n >= NN) return;
    int beg = g_rowptr[n], end = g_rowptr[n + 1];
    for (int i = beg + 1; i < end; i++) {
        int key = g_col[i];
        int j = i - 1;
        while (j >= beg && g_col[j] > key) { g_col[j + 1] = g_col[j]; j--; }
        g_col[j + 1] = key;
    }
}

// ---------------- weight transpose ----------------
__global__ void transpose_kernel(const float* __restrict__ w, float* __restrict__ wt) {
    int i = blockIdx.x * blockDim.x + threadIdx.x;
    if (i < DD * DD) {
        int r = i >> 8, c = i & 255;
        wt[c * DD + r] = w[i];
    }
}

// ---------------- fp32 SGEMM (x @ W, K=256) ----------------
#define BM 128
#define BN 128
#define BK 16
__global__ __launch_bounds__(256) void sgemm_nt(const float* __restrict__ A,
                                                const float* __restrict__ Bt,
                                                float* __restrict__ Cc,
                                                int M, int Nn) {
    __shared__ float As[BK][BM + 4];
    __shared__ float Bs[BK][BN + 4];
    int bm = blockIdx.y * BM;
    int bn = blockIdx.x * BN;
    int tid = threadIdx.x;
    int tr = tid >> 4;
    int tc = tid & 15;
    float acc[8][8];
#pragma unroll
    for (int i = 0; i < 8; i++)
#pragma unroll
        for (int j = 0; j < 8; j++) acc[i][j] = 0.0f;

    int lrow = tid >> 1;
    int lkq = (tid & 1) * 2;

    for (int k0 = 0; k0 < DD; k0 += BK) {
#pragma unroll
        for (int q = 0; q < 2; q++) {
            float4 v = make_float4(0.f, 0.f, 0.f, 0.f);
            int gr = bm + lrow;
            if (gr < M) v = *(const float4*)&A[(size_t)gr * DD + k0 + (lkq + q) * 4];
            int kb = (lkq + q) * 4;
            As[kb + 0][lrow] = v.x; As[kb + 1][lrow] = v.y;
            As[kb + 2][lrow] = v.z; As[kb + 3][lrow] = v.w;
        }
#pragma unroll
        for (int q = 0; q < 2; q++) {
            float4 v = make_float4(0.f, 0.f, 0.f, 0.f);
            int gn = bn + lrow;
            if (gn < Nn) v = *(const float4*)&Bt[(size_t)gn * DD + k0 + (lkq + q) * 4];
            int kb = (lkq + q) * 4;
            Bs[kb + 0][lrow] = v.x; Bs[kb + 1][lrow] = v.y;
            Bs[kb + 2][lrow] = v.z; Bs[kb + 3][lrow] = v.w;
        }
        __syncthreads();
#pragma unroll
        for (int kk = 0; kk < BK; kk++) {
            float a[8], b[8];
#pragma unroll
            for (int i = 0; i < 8; i++) a[i] = As[kk][tr * 8 + i];
#pragma unroll
            for (int j = 0; j < 8; j++) b[j] = Bs[kk][tc * 8 + j];
#pragma unroll
            for (int i = 0; i < 8; i++)
#pragma unroll
                for (int j = 0; j < 8; j++) acc[i][j] = fmaf(a[i], b[j], acc[i][j]);
        }
        __syncthreads();
    }
#pragma unroll
    for (int i = 0; i < 8; i++) {
        int gr = bm + tr * 8 + i;
        if (gr >= M) continue;
#pragma unroll
        for (int j = 0; j < 8; j++) {
            int gn = bn + tc * 8 + j;
            if (gn < Nn) Cc[(size_t)gr * Nn + gn] = acc[i][j];
        }
    }
}

// ---------------- GCN aggregation + bias + relu ----------------
__global__ void agg_kernel(const float* __restrict__ xw,
                           float* __restrict__ outp,
                           const float* __restrict__ bias) {
    int n = blockIdx.x;
    int d = threadIdx.x;
    float dn = g_disqrt[n];
    float acc = dn * dn * xw[(size_t)n * DD + d];
    int beg = g_rowptr[n], end = g_rowptr[n + 1];
    for (int j = beg; j < end; j++) {
        int s = g_col[j];
        acc += dn * g_disqrt[s] * xw[(size_t)s * DD + d];
    }
    outp[(size_t)n * DD + d] = fmaxf(acc + bias[d], 0.0f);
}

// ---------------- row L2 normalize + bf16 split ----------------
__global__ void norm_split_kernel(const float* __restrict__ in,
                                  __nv_bfloat16* __restrict__ outp,
                                  int hi2_off, int lo_off, int accum_s) {
    int r = blockIdx.x;
    int t = threadIdx.x;
    float v = in[(size_t)r * DD + t];
    __shared__ float sh[DD];
    sh[t] = v * v;
    __syncthreads();
    for (int off = 128; off > 0; off >>= 1) {
        if (t < off) sh[t] += sh[t + off];
        __syncthreads();
    }
    float nrm = sqrtf(sh[0]);
    float val = v / fmaxf(nrm, 1e-12f);
    __nv_bfloat16 hi = __float2bfloat16(val);
    __nv_bfloat16 lo = __float2bfloat16(val - __bfloat162float(hi));
    size_t base = (size_t)r * KTOT;
    outp[base + t] = hi;
    outp[base + hi2_off + t] = hi;
    outp[base + lo_off + t] = lo;
    if (accum_s) atomicAdd(&g_s[t], val);
}

// ---------------- bf16 HMMA sim GEMM: g_sim[B, LDN] = A' @ B'^T (K=768) ----------------
// CTA tile 128x128, 8 warps of 32x64, BK=32, double-buffered cp.async, ldmatrix feed.
#define BKK 32
#define LDK 40   // padded row stride in bf16 (80B) -> conflict-free ldmatrix
#define KITERS (KTOT / BKK)   // 24

__global__ __launch_bounds__(256) void sim_hmma_kernel(const __nv_bfloat16* __restrict__ Abf,
                                                       const __nv_bfloat16* __restrict__ Bbf,
                                                       float* __restrict__ simout) {
    __shared__ __nv_bfloat16 sA[2][128 * LDK];
    __shared__ __nv_bfloat16 sB[2][128 * LDK];

    const int tid = threadIdx.x;
    const int wid = tid >> 5;
    const int lane = tid & 31;
    const int bm = blockIdx.y * 128;
    const int bn = blockIdx.x * 128;

    const int wm = (wid & 3) * 32;   // warp m offset
    const int wn = (wid >> 2) * 64;  // warp n offset

    const uint32_t sA0 = smem_to_u32(&sA[0][0]);
    const uint32_t sA1 = smem_to_u32(&sA[1][0]);
    const uint32_t sB0 = smem_to_u32(&sB[0][0]);
    const uint32_t sB1 = smem_to_u32(&sB[1][0]);

    // copy indices: 512 16B-chunks per tile, 2 per thread
    const int r0c = tid >> 2;          // chunk row for q=0 (0..63)
    const int c0c = tid & 3;           // chunk col

    float acc[2][8][4];
#pragma unroll
    for (int mt = 0; mt < 2; mt++)
#pragma unroll
        for (int nt = 0; nt < 8; nt++)
#pragma unroll
            for (int e = 0; e < 4; e++) acc[mt][nt][e] = 0.0f;

    // prologue: load stage 0
    {
        const int k0 = 0;
#pragma unroll
        for (int q = 0; q < 2; q++) {
            int row = r0c + q * 64;
            int col = c0c * 8;
            cp_async16(sA0 + (uint32_t)(row * LDK + col) * 2,
                       &Abf[(size_t)(bm + row) * KTOT + k0 + col]);
            cp_async16(sB0 + (uint32_t)(row * LDK + col) * 2,
                       &Bbf[(size_t)(bn + row) * KTOT + k0 + col]);
        }
        cp_commit();
    }

    for (int kb = 0; kb < KITERS; kb++) {
        cp_wait0();
        __syncthreads();
        // prefetch next stage
        if (kb + 1 < KITERS) {
            const int k0 = (kb + 1) * BKK;
            uint32_t dA = ((kb + 1) & 1) ? sA1 : sA0;
            uint32_t dB = ((kb + 1) & 1) ? sB1 : sB0;
#pragma unroll
            for (int q = 0; q < 2; q++) {
                int row = r0c + q * 64;
                int col = c0c * 8;
                cp_async16(dA + (uint32_t)(row * LDK + col) * 2,
                           &Abf[(size_t)(bm + row) * KTOT + k0 + col]);
                cp_async16(dB + (uint32_t)(row * LDK + col) * 2,
                           &Bbf[(size_t)(bn + row) * KTOT + k0 + col]);
            }
            cp_commit();
        }
        // compute current stage
        uint32_t aBase = (kb & 1) ? sA1 : sA0;
        uint32_t bBase = (kb & 1) ? sB1 : sB0;
#pragma unroll
        for (int ks = 0; ks < BKK; ks += 16) {
            uint32_t afr[2][4];
#pragma unroll
            for (int mt = 0; mt < 2; mt++) {
                int r = wm + mt * 16 + (lane & 15);
                int c = ks + 8 * (lane >> 4);
                ldm_x4(afr[mt][0], afr[mt][1], afr[mt][2], afr[mt][3],
                       aBase + (uint32_t)(r * LDK + c) * 2);
            }
            uint32_t bfr[8][2];
#pragma unroll
            for (int bt = 0; bt < 4; bt++) {
                int r = wn + bt * 16 + ((lane >> 4) & 1) * 8 + (lane & 7);
                int c = ks + ((lane >> 3) & 1) * 8;
                ldm_x4(bfr[bt * 2][0], bfr[bt * 2][1], bfr[bt * 2 + 1][0], bfr[bt * 2 + 1][1],
                       bBase + (uint32_t)(r * LDK + c) * 2);
            }
#pragma unroll
            for (int mt = 0; mt < 2; mt++)
#pragma unroll
                for (int nt = 0; nt < 8; nt++)
                    mma16816(acc[mt][nt], afr[mt], bfr[nt]);
        }
        __syncthreads();
    }

    // epilogue: direct stores (float2 per mma row half)
#pragma unroll
    for (int mt = 0; mt < 2; mt++) {
        int row0 = bm + wm + mt * 16 + (lane >> 2);
#pragma unroll
        for (int nt = 0; nt < 8; nt++) {
            int col = bn + wn + nt * 8 + 2 * (lane & 3);
            *(float2*)&simout[(size_t)row0 * LDN + col] =
                make_float2(acc[mt][nt][0], acc[mt][nt][1]);
            *(float2*)&simout[(size_t)(row0 + 8) * LDN + col] =
                make_float2(acc[mt][nt][2], acc[mt][nt][3]);
        }
    }
}

// ---------------- per-class max over 10 prototypes ----------------
__global__ void reduce_max_kernel(float* __restrict__ out) {
    int i = blockIdx.x * blockDim.x + threadIdx.x;
    if (i >= BB * CC) return;
    int b = i / CC, c = i % CC;
    const float* p = &g_sim[(size_t)b * LDN + c * PP];
    float best = -1e30f;
    int bi = 0;
#pragma unroll
    for (int j = 0; j < PP; j++) {
        float v = p[j];
        if (v > best) { best = v; bi = j; }
    }
    out[i] = 0.5f * (1.0f + best);
    g_argp[i] = (unsigned char)bi;
}

// ---------------- per-row CE + usage scatter ----------------
__global__ void ce_kernel(const float* __restrict__ out,
                          const int* __restrict__ labels,
                          float* __restrict__ usage_pos,
                          float* __restrict__ usage_neg) {
    int b = blockIdx.x;
    const float* row = out + (size_t)b * CC;
    int t = threadIdx.x;
    __shared__ float smax[256];
    __shared__ int simax[256];
    float bm = -1e30f;
    int bi = 0x7fffffff;
    for (int c = t; c < CC; c += 256) {
        float v = row[c];
        if (v > bm) { bm = v; bi = c; }
    }
    smax[t] = bm; simax[t] = bi;
    __syncthreads();
    for (int off = 128; off > 0; off >>= 1) {
        if (t < off) {
            float v2 = smax[t + off];
            int i2 = simax[t + off];
            if (v2 > smax[t] || (v2 == smax[t] && i2 < simax[t])) {
                smax[t] = v2; simax[t] = i2;
            }
        }
        __syncthreads();
    }
    float rowmax = smax[0];
    int pred = simax[0];
    __shared__ float ssum[256];
    float s = 0.0f;
    for (int c = t; c < CC; c += 256) s += expf(row[c] - rowmax);
    ssum[t] = s;
    __syncthreads();
    for (int off = 128; off > 0; off >>= 1) {
        if (t < off) ssum[t] += ssum[t + off];
        __syncthreads();
    }
    if (t == 0) {
        int lab = labels[b];
        float x_lab = row[lab];
        float lse = rowmax + logf(ssum[0]);
        if ((x_lab - rowmax) > MARGIN_F) {
            atomicAdd(&g_ce_sum, lse - x_lab);
            atomicAdd(&g_cnt, 1);
        }
        atomicAdd(&usage_pos[lab * PP + (int)g_argp[b * CC + lab]], 1.0f);
        if (pred != lab)
            atomicAdd(&usage_neg[pred * PP + (int)g_argp[b * CC + pred]], 1.0f);
    }
}

// ---------------- finalize loss ----------------
__global__ void finalize_kernel(float* __restrict__ out_loss) {
    __shared__ float sh[DD];
    int t = threadIdx.x;
    float v = g_s[t];
    sh[t] = v * v;
    __syncthreads();
    for (int off = 128; off > 0; off >>= 1) {
        if (t < off) sh[t] += sh[t + off];
        __syncthreads();
    }
    if (t == 0) {
        float disp = -sh[0] / ((float)NN * (float)NN);
        int cnt = g_cnt;
        float loss = (cnt == 0) ? 0.0f
                                : (g_ce_sum / (float)(cnt > 1 ? cnt : 1) + LW_F * disp);
        out_loss[0] = loss;
    }
}

// ---------------- launch ----------------
extern "C" void kernel_launch(void* const* d_in, const int* in_sizes, int n_in,
                              void* d_out, int out_size) {
    const float* hidden = (const float*)d_in[0];
    const int* labels = (const int*)d_in[1];
    const int* edge_index = (const int*)d_in[2];
    const float* node_features = (const float*)d_in[3];
    const float* w1 = (const float*)d_in[4];
    const float* b1 = (const float*)d_in[5];
    const float* w2 = (const float*)d_in[6];
    const float* b2 = (const float*)d_in[7];
    float* out = (float*)d_out;

    float* out_loss = out + (size_t)BB * CC;
    float* out_pos = out_loss + 1;
    float* out_neg = out_pos + NN;

    float *p_bufA = 0, *p_bufB = 0, *p_sim = 0, *p_wt = 0;
    __nv_bfloat16 *p_Abf = 0, *p_Bbf = 0;
    cudaGetSymbolAddress((void**)&p_bufA, g_bufA);
    cudaGetSymbolAddress((void**)&p_bufB, g_bufB);
    cudaGetSymbolAddress((void**)&p_sim,  g_sim);
    cudaGetSymbolAddress((void**)&p_wt,   g_wt);
    cudaGetSymbolAddress((void**)&p_Abf,  g_Abf);
    cudaGetSymbolAddress((void**)&p_Bbf,  g_Bbf);

    // graph build
    init_kernel<<<(1 + 2 * NN + 255) / 256, 256>>>(out_loss);
    deg_kernel<<<(EE + 255) / 256, 256>>>(edge_index);
    disqrt_kernel<<<(NN + 255) / 256, 256>>>();
    scan_kernel<<<1, 1024>>>();
    scatter_kernel<<<(EE + 255) / 256, 256>>>(edge_index);
    sort_kernel<<<(NN + 255) / 256, 256>>>();

    // GCN layer 1
    transpose_kernel<<<(DD * DD + 255) / 256, 256>>>(w1, p_wt);
    {
        dim3 grid((DD + BN - 1) / BN, (NN + BM - 1) / BM);
        sgemm_nt<<<grid, 256>>>(node_features, p_wt, p_bufA, NN, DD);
    }
    agg_kernel<<<NN, DD>>>(p_bufA, p_bufB, b1);
    // GCN layer 2
    transpose_kernel<<<(DD * DD + 255) / 256, 256>>>(w2, p_wt);
    {
        dim3 grid((DD + BN - 1) / BN, (NN + BM - 1) / BM);
        sgemm_nt<<<grid, 256>>>(p_bufB, p_wt, p_bufA, NN, DD);
    }
    agg_kernel<<<NN, DD>>>(p_bufA, p_bufB, b2);

    // normalize + bf16 split:
    //   protos (B'): [hi | lo | hi]  -> hi2_off=512, lo_off=256 ; accumulate g_s
    //   hidden (A'): [hi | hi | lo]  -> hi2_off=256, lo_off=512
    norm_split_kernel<<<NN, DD>>>(p_bufB, p_Bbf, 512, 256, 1);
    norm_split_kernel<<<BB, DD>>>(hidden, p_Abf, 256, 512, 0);

    // tensor-core (HMMA) sim GEMM: g_sim[4096, 10112] = A' @ B'^T
    {
        dim3 grid(LDN / 128, BB / 128);
        sim_hmma_kernel<<<grid, 256>>>(p_Abf, p_Bbf, p_sim);
    }

    // per-class max + argmax
    reduce_max_kernel<<<(BB * CC + 255) / 256, 256>>>(out);

    // CE + usage
    ce_kernel<<<BB, 256>>>(out, labels, out_pos, out_neg);

    // loss
    finalize_kernel<<<1, DD>>>(out_loss);
}